// round 17
// baseline (speedup 1.0000x reference)
#include <cuda_runtime.h>
#include <cuda_fp16.h>
#include <cstdint>

// SDFGrid R14: two-pass (R13 won: 96.8us, pass2 DRAM-bound at 75%).
// Pass 1: unchanged — per-voxel (nx,ny,nz,relu(-g)) packed 4xfp16 = 8B.
// Pass 2: 8 unconditional uint2 gathers (entries z and z+1 of each corner
//         column) instead of pair-aligned uint4 + odd-z supplement:
//         avg sectors/corner 1.5 -> 1.25, no branch, no select network.

#define GR      256
#define BBMIN  -2.0f
#define VS      (4.0f / 255.0f)
#define INV_VS  63.75f
#define INV_2VS 31.875f

// packed normal grid: entry v = { h2(nx,ny), h2(nz, relu(-g)) }, flat index
// v = z + 256*y + 65536*x  (same as grid)
__device__ uint2 g_pk[1 << 24];

__device__ __forceinline__ unsigned pk2(float a, float b) {
    __half2 h = __floats2half2_rn(a, b);   // .x = a (low), .y = b (high)
    return *reinterpret_cast<unsigned*>(&h);
}

// ============================ pass 1 ====================================
// one thread per (x, y, 4-z-chunk); 256*256*64 threads
__global__ void __launch_bounds__(256) pack_normals(const float* __restrict__ g)
{
    int idx = blockIdx.x * 256 + threadIdx.x;
    int z0 = (idx & 63) << 2;
    int y  = (idx >> 6) & 255;
    int x  = idx >> 14;

    const float* base = g + ((x << 16) | (y << 8));

    // center column values z0-1 .. z0+4
    float4 W = __ldg((const float4*)(base + z0));
    float c1 = W.x, c2 = W.y, c3 = W.z, c4 = W.w;
    float c0 = (z0 > 0)   ? __ldg(base + z0 - 1) : 0.0f;
    float c5 = (z0 < 252) ? __ldg(base + z0 + 4) : 0.0f;

    // neighbor columns (clamped pointers; boundary values handled by formula)
    int xm = (x > 0)   ? x - 1 : 0;
    int xp = (x < 255) ? x + 1 : 255;
    int ym = (y > 0)   ? y - 1 : 0;
    int yp = (y < 255) ? y + 1 : 255;
    float4 XM = __ldg((const float4*)(g + ((xm << 16) | (y << 8)) + z0));
    float4 XP = __ldg((const float4*)(g + ((xp << 16) | (y << 8)) + z0));
    float4 YM = __ldg((const float4*)(g + ((x << 16) | (ym << 8)) + z0));
    float4 YP = __ldg((const float4*)(g + ((x << 16) | (yp << 8)) + z0));

    // 2-away columns for one-sided boundary diffs (rare rows only)
    float4 X2 = make_float4(0, 0, 0, 0), Y2 = make_float4(0, 0, 0, 0);
    bool xb = (x == 0) | (x == 255);
    bool yb = (y == 0) | (y == 255);
    if (xb) { int x2 = (x == 0) ? 2 : 253; X2 = __ldg((const float4*)(g + ((x2 << 16) | (y << 8)) + z0)); }
    if (yb) { int y2 = (y == 0) ? 2 : 253; Y2 = __ldg((const float4*)(g + ((x << 16) | (y2 << 8)) + z0)); }

    float cc[4] = {c1, c2, c3, c4};
    float xpv[4] = {XP.x, XP.y, XP.z, XP.w};
    float xmv[4] = {XM.x, XM.y, XM.z, XM.w};
    float x2v[4] = {X2.x, X2.y, X2.z, X2.w};
    float ypv[4] = {YP.x, YP.y, YP.z, YP.w};
    float ymv[4] = {YM.x, YM.y, YM.z, YM.w};
    float y2v[4] = {Y2.x, Y2.y, Y2.z, Y2.w};

    // nz numerators
    float nz[4];
    nz[0] = (z0 == 0)   ? (c2 - (1.5f * c1 - 0.5f * c3)) : (c2 - c0);
    nz[1] = c3 - c1;
    nz[2] = c4 - c2;
    nz[3] = (z0 == 252) ? ((1.5f * c4 - 0.5f * c2) - c3) : (c5 - c3);

    uint2 o[4];
#pragma unroll
    for (int i = 0; i < 4; ++i) {
        float onesx = 1.5f * cc[i] - 0.5f * x2v[i];
        float fwdx = (x == 255) ? onesx : xpv[i];
        float bwdx = (x == 0)   ? onesx : xmv[i];
        float nx = (fwdx - bwdx) * INV_2VS;

        float onesy = 1.5f * cc[i] - 0.5f * y2v[i];
        float fwdy = (y == 255) ? onesy : ypv[i];
        float bwdy = (y == 0)   ? onesy : ymv[i];
        float ny = (fwdy - bwdy) * INV_2VS;

        float nzi = nz[i] * INV_2VS;
        float gx  = fmaxf(-cc[i], 0.0f);

        o[i].x = pk2(nx, ny);
        o[i].y = pk2(nzi, gx);
    }

    uint4* dst = (uint4*)(g_pk + ((x << 16) | (y << 8) | z0));  // 32B aligned
    dst[0] = make_uint4(o[0].x, o[0].y, o[1].x, o[1].y);
    dst[1] = make_uint4(o[2].x, o[2].y, o[3].x, o[3].y);
}

// ============================ pass 2 ====================================
__device__ __forceinline__ float2 up2(unsigned u) {
    return __half22float2(*reinterpret_cast<__half2*>(&u));
}

__global__ void __launch_bounds__(256, 6) gather_kernel(
    const int* __restrict__ voxel_idx,
    const float* __restrict__ ipos,
    const int* __restrict__ mask,
    float4* __restrict__ out,
    int n)
{
    int p = blockIdx.x * blockDim.x + threadIdx.x;
    if (p >= n) return;

    int x = __ldcs(voxel_idx + 3 * p + 0);
    int y = __ldcs(voxel_idx + 3 * p + 1);
    int z = __ldcs(voxel_idx + 3 * p + 2);

    float tx = (__ldcs(ipos + 3 * p + 0) - fmaf((float)x, VS, BBMIN)) * INV_VS;
    float ty = (__ldcs(ipos + 3 * p + 1) - fmaf((float)y, VS, BBMIN)) * INV_VS;
    float tz = (__ldcs(ipos + 3 * p + 2) - fmaf((float)z, VS, BBMIN)) * INV_VS;

    int v00 = (x << 16) | (y << 8) | z;
    int v01 = v00 + 256;
    int v10 = v00 + 65536;
    int v11 = v10 + 256;

    // 8 unconditional uint2 loads: voxels z and z+1 of each corner column
    uint2 A00 = __ldg(g_pk + v00), B00 = __ldg(g_pk + v00 + 1);
    uint2 A01 = __ldg(g_pk + v01), B01 = __ldg(g_pk + v01 + 1);
    uint2 A10 = __ldg(g_pk + v10), B10 = __ldg(g_pk + v10 + 1);
    uint2 A11 = __ldg(g_pk + v11), B11 = __ldg(g_pk + v11 + 1);

    float wz0 = 1.0f - tz;

    // z-blends per corner column
    float2 a, b;
    a = up2(A00.x); b = up2(B00.x);
    float fx0 = wz0 * a.x + tz * b.x, fy0 = wz0 * a.y + tz * b.y;
    a = up2(A00.y); b = up2(B00.y);
    float fz0 = wz0 * a.x + tz * b.x;
    float g000 = a.y;                       // relu(-g) at base corner (z word)

    a = up2(A01.x); b = up2(B01.x);
    float fx1 = wz0 * a.x + tz * b.x, fy1 = wz0 * a.y + tz * b.y;
    a = up2(A01.y); b = up2(B01.y);
    float fz1 = wz0 * a.x + tz * b.x;

    a = up2(A10.x); b = up2(B10.x);
    float fx2 = wz0 * a.x + tz * b.x, fy2 = wz0 * a.y + tz * b.y;
    a = up2(A10.y); b = up2(B10.y);
    float fz2 = wz0 * a.x + tz * b.x;

    a = up2(A11.x); b = up2(B11.x);
    float fx3 = wz0 * a.x + tz * b.x, fy3 = wz0 * a.y + tz * b.y;
    a = up2(A11.y); b = up2(B11.y);
    float fz3 = wz0 * a.x + tz * b.x;

    float w00 = (1.0f - tx) * (1.0f - ty);
    float w01 = (1.0f - tx) * ty;
    float w10 = tx * (1.0f - ty);
    float w11 = tx * ty;

    float m   = (float)__ldcs(mask + p);
    float inv = 1.0f - m;

    float ox = w00 * fx0 + w01 * fx1 + w10 * fx2 + w11 * fx3 + inv;
    float oy = w00 * fy0 + w01 * fy1 + w10 * fy2 + w11 * fy3 + inv;
    float oz = w00 * fz0 + w01 * fz1 + w10 * fz2 + w11 * fz3 + inv;
    float ow = g000 * m;

    __stcs(out + p, make_float4(ox, oy, oz, ow));
}

extern "C" void kernel_launch(void* const* d_in, const int* in_sizes, int n_in,
                              void* d_out, int out_size) {
    const float* grid = (const float*)d_in[0];
    const int*   vidx = (const int*)d_in[1];
    const float* ipos = (const float*)d_in[2];
    const int*   mask = (const int*)d_in[4];

    int n = in_sizes[4];          // H*W pixels
    float4* out = (float4*)d_out;

    // pass 1: 256*256*64 threads = 16384 blocks of 256
    pack_normals<<<16384, 256>>>(grid);

    // pass 2: one thread per pixel
    int threads = 256;
    int blocks = (n + threads - 1) / threads;
    gather_kernel<<<blocks, threads>>>(vidx, ipos, mask, out, n);
}